// round 3
// baseline (speedup 1.0000x reference)
#include <cuda_runtime.h>
#include <math.h>

#define BB 512
#define NN 64
#define EE 512
#define AA 16
#define ITERS 8

// ---------------- scratch (static device globals; no allocation) ------------
__device__ float g_q[BB * NN * AA];       // current per-node action values (2 MB)
__device__ float g_mf[BB * EE * AA];      // forward messages (16 MB)
__device__ float g_mb[BB * EE * AA];      // backward messages (16 MB)
__device__ int   g_acur[BB * NN];         // current argmax action per node
__device__ float g_qmax[BB];              // best q value so far
__device__ int   g_amax[BB * NN];         // best action assignment so far
__device__ int   g_in_cnt[NN];            // adjacency CSR (deterministic order)
__device__ int   g_out_cnt[NN];
__device__ int   g_in_list[NN * EE];
__device__ int   g_out_list[NN * EE];

// ---------------- zero messages ---------------------------------------------
__global__ void k_zero() {
    int i = blockIdx.x * blockDim.x + threadIdx.x;          // float4 index
    float4 z = make_float4(0.f, 0.f, 0.f, 0.f);
    ((float4*)g_mf)[i] = z;
    ((float4*)g_mb)[i] = z;
}

// ---------------- init: q0 = node_vals/N, a_cur = argmax(node_vals) ---------
__global__ void k_init(const float* __restrict__ node_vals) {
    int b = blockIdx.x;
    int tid = threadIdx.x;                  // 1024 = NN*AA
    int n = tid >> 4, a = tid & 15;
    size_t idx = ((size_t)b * NN + n) * AA + a;
    float v = node_vals[idx];
    g_q[idx] = v * (1.0f / NN);
    float bv = v; int bi = a;
    const unsigned full = 0xffffffffu;
    #pragma unroll
    for (int m = 1; m < 16; m <<= 1) {
        float ov = __shfl_xor_sync(full, bv, m, 16);
        int   oi = __shfl_xor_sync(full, bi, m, 16);
        if (ov > bv || (ov == bv && oi < bi)) { bv = ov; bi = oi; }
    }
    if (a == 0) g_acur[b * NN + n] = bi;
    if (tid == 0) g_qmax[b] = -INFINITY;
}

// ---------------- adjacency build (deterministic, ascending e order) --------
__global__ void k_adj(const int* __restrict__ ef, const int* __restrict__ et) {
    int tid = threadIdx.x;                  // 128 threads
    if (tid < NN) {
        int c = 0;
        for (int e = 0; e < EE; e++) if (et[e] == tid) g_in_list[tid * EE + c++] = e;
        g_in_cnt[tid] = c;
    } else if (tid < 2 * NN) {
        int n = tid - NN; int c = 0;
        for (int e = 0; e < EE; e++) if (ef[e] == n) g_out_list[n * EE + c++] = e;
        g_out_cnt[n] = c;
    }
}

// ---------------- message kernel: one warp per (b,e) 16x16 tile -------------
__global__ void __launch_bounds__(256) k_msg(
    const float* __restrict__ edge_vals,
    const int* __restrict__ ef, const int* __restrict__ et)
{
    int gw   = (blockIdx.x * blockDim.x + threadIdx.x) >> 5;   // global warp id
    int lane = threadIdx.x & 31;
    int b = gw >> 9;          // / EE
    int e = gw & (EE - 1);

    const float4* tile = (const float4*)(edge_vals + (((size_t)b * EE + e) << 8));
    float4 v0 = tile[lane];        // row r0 = lane>>2, cols (lane&3)*4 ..
    float4 v1 = tile[32 + lane];   // row r0+8
    const float sc = 1.0f / EE;    // edge_vals_E = edge_vals / E
    v0.x *= sc; v0.y *= sc; v0.z *= sc; v0.w *= sc;
    v1.x *= sc; v1.y *= sc; v1.z *= sc; v1.w *= sc;

    int r0 = lane >> 2;            // row within 0..7
    int k  = lane & 3;             // column group (cols 4k..4k+3)

    int nf = ef[e], nt = et[e];
    const float* qf = g_q + (((size_t)b * NN + nf) << 4);
    const float* qt = g_q + (((size_t)b * NN + nt) << 4);
    float* mfp = g_mf + (((size_t)b * EE + e) << 4);
    float* mbp = g_mb + (((size_t)b * EE + e) << 4);

    // d[at] = q[to][at] - mf_old[at]   (for this lane's 4 columns)
    float4 qt4  = ((const float4*)qt)[k];
    float4 mfo4 = ((const float4*)mfp)[k];
    float4 d4 = make_float4(qt4.x - mfo4.x, qt4.y - mfo4.y,
                            qt4.z - mfo4.z, qt4.w - mfo4.w);
    // c[af] = q[from][af] - mb_old[af]  (for this lane's 2 rows)
    float c0 = qf[r0]     - mbp[r0];
    float c1 = qf[r0 + 8] - mbp[r0 + 8];

    const unsigned full = 0xffffffffu;

    // mb_new[af] = max_at( d[at] + ev[af][at] )
    float m0 = fmaxf(fmaxf(d4.x + v0.x, d4.y + v0.y), fmaxf(d4.z + v0.z, d4.w + v0.w));
    float m1 = fmaxf(fmaxf(d4.x + v1.x, d4.y + v1.y), fmaxf(d4.z + v1.z, d4.w + v1.w));
    m0 = fmaxf(m0, __shfl_xor_sync(full, m0, 1));
    m0 = fmaxf(m0, __shfl_xor_sync(full, m0, 2));
    m1 = fmaxf(m1, __shfl_xor_sync(full, m1, 1));
    m1 = fmaxf(m1, __shfl_xor_sync(full, m1, 2));

    // mf_new[at] = max_af( c[af] + ev[af][at] )
    float4 f;
    f.x = fmaxf(c0 + v0.x, c1 + v1.x);
    f.y = fmaxf(c0 + v0.y, c1 + v1.y);
    f.z = fmaxf(c0 + v0.z, c1 + v1.z);
    f.w = fmaxf(c0 + v0.w, c1 + v1.w);
    #pragma unroll
    for (int m = 4; m <= 16; m <<= 1) {
        f.x = fmaxf(f.x, __shfl_xor_sync(full, f.x, m));
        f.y = fmaxf(f.y, __shfl_xor_sync(full, f.y, m));
        f.z = fmaxf(f.z, __shfl_xor_sync(full, f.z, m));
        f.w = fmaxf(f.w, __shfl_xor_sync(full, f.w, m));
    }

    // mean-center mf over the 16 'at' values
    float s = f.x + f.y + f.z + f.w;
    s += __shfl_xor_sync(full, s, 1);
    s += __shfl_xor_sync(full, s, 2);
    s *= (1.0f / AA);
    f.x -= s; f.y -= s; f.z -= s; f.w -= s;

    // mean-center mb over the 16 'af' values
    float sm = m0 + m1;
    sm += __shfl_xor_sync(full, sm, 4);
    sm += __shfl_xor_sync(full, sm, 8);
    sm += __shfl_xor_sync(full, sm, 16);
    sm *= (1.0f / AA);
    m0 -= sm; m1 -= sm;

    if (r0 == 0) ((float4*)mfp)[k] = f;     // lanes 0..3 write mf[4k..4k+3]
    if (k == 0) { mbp[r0] = m0; mbp[r0 + 8] = m1; }
}

// ---------------- node update + argmax --------------------------------------
__global__ void k_node(const float* __restrict__ node_vals) {
    int b = blockIdx.x;
    int tid = threadIdx.x;                  // 1024 = NN*AA
    int n = tid >> 4, a = tid & 15;
    float v = node_vals[((size_t)b * NN + n) * AA + a] * (1.0f / NN);
    const float* mfb = g_mf + ((size_t)b * EE << 4);
    const float* mbb = g_mb + ((size_t)b * EE << 4);
    int ic = g_in_cnt[n];
    const int* il = g_in_list + n * EE;
    for (int i = 0; i < ic; i++) v += mfb[(il[i] << 4) + a];   // .at[to].add(mf)
    int oc = g_out_cnt[n];
    const int* ol = g_out_list + n * EE;
    for (int i = 0; i < oc; i++) v += mbb[(ol[i] << 4) + a];   // .at[from].add(mb)
    g_q[((size_t)b * NN + n) * AA + a] = v;

    float bv = v; int bi = a;
    const unsigned full = 0xffffffffu;
    #pragma unroll
    for (int m = 1; m < 16; m <<= 1) {
        float ov = __shfl_xor_sync(full, bv, m, 16);
        int   oi = __shfl_xor_sync(full, bi, m, 16);
        if (ov > bv || (ov == bv && oi < bi)) { bv = ov; bi = oi; }
    }
    if (a == 0) g_acur[b * NN + n] = bi;
}

// ---------------- evaluate current assignment, keep best --------------------
__global__ void k_eval(const float* __restrict__ node_vals,
                       const float* __restrict__ edge_vals,
                       const int* __restrict__ ef, const int* __restrict__ et)
{
    int b = blockIdx.x;
    int tid = threadIdx.x;                  // 128 threads
    __shared__ int   sa[NN];
    __shared__ float rN[128], rE[128];
    __shared__ int   flag;
    if (tid < NN) sa[tid] = g_acur[b * NN + tid];
    __syncthreads();

    float ns = 0.f, es = 0.f;
    if (tid < NN) ns = node_vals[((size_t)b * NN + tid) * AA + sa[tid]];
    for (int e = tid; e < EE; e += 128) {
        int af = sa[ef[e]], at = sa[et[e]];
        es += edge_vals[((((size_t)b * EE + e) << 4) + af << 4) + at];
    }
    rN[tid] = ns; rE[tid] = es;
    __syncthreads();
    for (int s = 64; s > 0; s >>= 1) {
        if (tid < s) { rN[tid] += rN[tid + s]; rE[tid] += rE[tid + s]; }
        __syncthreads();
    }
    if (tid == 0) {
        float qv = rN[0] * (1.0f / NN) + rE[0] * (1.0f / EE);
        flag = (qv > g_qmax[b]) ? 1 : 0;
        if (flag) g_qmax[b] = qv;
    }
    __syncthreads();
    if (flag && tid < NN) g_amax[b * NN + tid] = sa[tid];
}

// ---------------- output: concat(q_max[B], a_max[B*N]) as float32 -----------
__global__ void k_out(float* __restrict__ out, int out_size) {
    int i = blockIdx.x * blockDim.x + threadIdx.x;
    if (i >= out_size) return;
    if (out_size >= BB + BB * NN) {
        if (i < BB)               out[i] = g_qmax[i];
        else if (i < BB + BB*NN)  out[i] = (float)g_amax[i - BB];
    } else if (out_size == BB * NN) {
        out[i] = (float)g_amax[i];
    } else {
        if (i < BB) out[i] = g_qmax[i];
    }
}

// ---------------- launch ----------------------------------------------------
extern "C" void kernel_launch(void* const* d_in, const int* in_sizes, int n_in,
                              void* d_out, int out_size) {
    const float* node_vals = (const float*)d_in[0];
    const float* edge_vals = (const float*)d_in[1];
    const int*   ef        = (const int*)d_in[2];
    const int*   et        = (const int*)d_in[3];
    float* out = (float*)d_out;

    // zero messages: BB*EE*AA floats = 4 Mi floats -> 1 Mi float4
    k_zero<<<(BB * EE * AA / 4) / 256, 256>>>();
    k_init<<<BB, NN * AA>>>(node_vals);
    k_adj<<<1, 128>>>(ef, et);
    k_eval<<<BB, 128>>>(node_vals, edge_vals, ef, et);

    for (int it = 0; it < ITERS; it++) {
        k_msg<<<(BB * EE) / 8, 256>>>(edge_vals, ef, et);   // 8 warps/block
        k_node<<<BB, NN * AA>>>(node_vals);
        k_eval<<<BB, 128>>>(node_vals, edge_vals, ef, et);
    }

    int tot = BB + BB * NN;
    int span = (out_size > tot) ? out_size : tot;
    k_out<<<(span + 255) / 256, 256>>>(out, out_size);
}

// round 5
// speedup vs baseline: 1.3571x; 1.3571x over previous
#include <cuda_runtime.h>
#include <math.h>

#define BB 512
#define NN 64
#define EE 512
#define AA 16
#define ITERS 8

// ---------------- small global scratch (no allocation) ----------------------
__device__ float g_qmax[BB];
__device__ int   g_amax[BB * NN];
__device__ int   g_in_cnt[NN];
__device__ int   g_out_cnt[NN];
__device__ int   g_in_list[NN * EE];
__device__ int   g_out_list[NN * EE];

// ---------------- adjacency build (deterministic, ascending e order) --------
__global__ void k_adj(const int* __restrict__ ef, const int* __restrict__ et) {
    int tid = threadIdx.x;                  // 128 threads
    if (tid < NN) {
        int c = 0;
        for (int e = 0; e < EE; e++) if (et[e] == tid) g_in_list[tid * EE + c++] = e;
        g_in_cnt[tid] = c;
    } else if (tid < 2 * NN) {
        int n = tid - NN; int c = 0;
        for (int e = 0; e < EE; e++) if (ef[e] == n) g_out_list[n * EE + c++] = e;
        g_out_cnt[n] = c;
    }
}

// Dynamic smem request: pad above 113.5 KB so only ONE CTA fits per SM.
// -> 148 resident batches x 512KB edge slice = 74 MB, fits in L2 (126 MB).
#define SMEM_BYTES (120 * 1024)

// ---------------- fused persistent kernel: one CTA per batch ----------------
__global__ void __launch_bounds__(1024, 1) k_main(
    const float* __restrict__ node_vals,
    const float* __restrict__ edge_vals,
    const int* __restrict__ ef_g,
    const int* __restrict__ et_g)
{
    extern __shared__ float smem[];
    float* s_mf  = smem;                    // EE*AA = 8192 floats (32 KB)
    float* s_mb  = s_mf + EE * AA;          // 8192 floats (32 KB)
    float* s_q   = s_mb + EE * AA;          // NN*AA = 1024 floats (4 KB)
    float* s_nv  = s_q  + NN * AA;          // 1024 floats (4 KB) raw node_vals
    int*   s_ef  = (int*)(s_nv + NN * AA);  // 512 ints
    int*   s_et  = s_ef + EE;               // 512 ints
    int*   s_a   = s_et + EE;               // 64 ints (current argmax)
    int*   s_am  = s_a  + NN;               // 64 ints (best actions)
    float* s_red = (float*)(s_am + NN);     // 32 floats (reduction)

    __shared__ float sh_qmax;
    __shared__ int   sh_flag;

    const int b    = blockIdx.x;
    const int tid  = threadIdx.x;           // 1024 = NN*AA
    const int lane = tid & 31;
    const int warp = tid >> 5;              // 0..31
    const unsigned full = 0xffffffffu;

    // ---------------- init ----------------
    {
        float v = node_vals[(size_t)b * NN * AA + tid];
        s_nv[tid] = v;
        s_q[tid]  = v * (1.0f / NN);
        float4 z = make_float4(0.f, 0.f, 0.f, 0.f);
        ((float4*)s_mf)[tid] = z; ((float4*)s_mf)[tid + 1024] = z;
        ((float4*)s_mb)[tid] = z; ((float4*)s_mb)[tid + 1024] = z;
        if (tid < EE) s_ef[tid] = ef_g[tid];
        else          s_et[tid - EE] = et_g[tid - EE];
        if (tid == 0) { sh_qmax = -INFINITY; sh_flag = 0; }

        // initial per-node argmax over RAW node_vals (matches reference a_max init)
        int a = tid & 15;
        float bv = v; int bi = a;
        #pragma unroll
        for (int m = 1; m < 16; m <<= 1) {
            float ov = __shfl_xor_sync(full, bv, m, 16);
            int   oi = __shfl_xor_sync(full, bi, m, 16);
            if (ov > bv || (ov == bv && oi < bi)) { bv = ov; bi = oi; }
        }
        if (a == 0) s_a[tid >> 4] = bi;
    }
    __syncthreads();

    // ---------------- eval lambda-like macro body as a loop-invoked section --
    // (written inline twice via a small helper)
    auto do_eval = [&]() {
        float contrib = 0.f;
        if (tid < NN)
            contrib += s_nv[tid * AA + s_a[tid]] * (1.0f / NN);
        if (tid < EE) {
            int e  = tid;
            int af = s_a[s_ef[e]];
            int at = s_a[s_et[e]];
            contrib += edge_vals[(((size_t)b * EE + e) * AA + af) * AA + at] * (1.0f / EE);
        }
        #pragma unroll
        for (int m = 16; m > 0; m >>= 1)
            contrib += __shfl_xor_sync(full, contrib, m);
        if (lane == 0) s_red[warp] = contrib;
        __syncthreads();
        if (warp == 0) {
            float v = s_red[lane];
            #pragma unroll
            for (int m = 16; m > 0; m >>= 1)
                v += __shfl_xor_sync(full, v, m);
            if (lane == 0) {
                if (v > sh_qmax) { sh_qmax = v; sh_flag = 1; }
                else             { sh_flag = 0; }
            }
        }
        __syncthreads();
        if (sh_flag && tid < NN) s_am[tid] = s_a[tid];
        __syncthreads();
    };

    do_eval();   // iteration-0 eval of raw argmax assignment

    // ---------------- 8 message-passing iterations ----------------
    for (int it = 0; it < ITERS; it++) {
        // ---- message phase: each warp owns 16 edges ----
        {
            int r0 = lane >> 2;            // row in 0..7 (also row+8)
            int k  = lane & 3;             // column group (4k..4k+3)
            #pragma unroll 2
            for (int i = 0; i < 16; i++) {
                int e = warp * 16 + i;
                const float4* tile = (const float4*)(edge_vals + (((size_t)b * EE + e) << 8));
                float4 v0 = tile[lane];
                float4 v1 = tile[32 + lane];
                const float sc = 1.0f / EE;
                v0.x *= sc; v0.y *= sc; v0.z *= sc; v0.w *= sc;
                v1.x *= sc; v1.y *= sc; v1.z *= sc; v1.w *= sc;

                int nf = s_ef[e], nt = s_et[e];
                const float* qf = s_q + (nf << 4);
                const float* qt = s_q + (nt << 4);
                float* mfp = s_mf + (e << 4);
                float* mbp = s_mb + (e << 4);

                // d[at] = q[to][at] - mf_old[at] (lane's 4 cols)
                float4 qt4  = ((const float4*)qt)[k];
                float4 mfo4 = ((const float4*)mfp)[k];
                float4 d4 = make_float4(qt4.x - mfo4.x, qt4.y - mfo4.y,
                                        qt4.z - mfo4.z, qt4.w - mfo4.w);
                // c[af] = q[from][af] - mb_old[af] (lane's 2 rows)
                float c0 = qf[r0]     - mbp[r0];
                float c1 = qf[r0 + 8] - mbp[r0 + 8];

                // mb_new[af] = max_at( d[at] + ev[af][at] )
                float m0 = fmaxf(fmaxf(d4.x + v0.x, d4.y + v0.y),
                                 fmaxf(d4.z + v0.z, d4.w + v0.w));
                float m1 = fmaxf(fmaxf(d4.x + v1.x, d4.y + v1.y),
                                 fmaxf(d4.z + v1.z, d4.w + v1.w));
                m0 = fmaxf(m0, __shfl_xor_sync(full, m0, 1));
                m0 = fmaxf(m0, __shfl_xor_sync(full, m0, 2));
                m1 = fmaxf(m1, __shfl_xor_sync(full, m1, 1));
                m1 = fmaxf(m1, __shfl_xor_sync(full, m1, 2));

                // mf_new[at] = max_af( c[af] + ev[af][at] )
                float4 f;
                f.x = fmaxf(c0 + v0.x, c1 + v1.x);
                f.y = fmaxf(c0 + v0.y, c1 + v1.y);
                f.z = fmaxf(c0 + v0.z, c1 + v1.z);
                f.w = fmaxf(c0 + v0.w, c1 + v1.w);
                #pragma unroll
                for (int m = 4; m <= 16; m <<= 1) {
                    f.x = fmaxf(f.x, __shfl_xor_sync(full, f.x, m));
                    f.y = fmaxf(f.y, __shfl_xor_sync(full, f.y, m));
                    f.z = fmaxf(f.z, __shfl_xor_sync(full, f.z, m));
                    f.w = fmaxf(f.w, __shfl_xor_sync(full, f.w, m));
                }

                // mean-center mf over 16 'at'
                float s = f.x + f.y + f.z + f.w;
                s += __shfl_xor_sync(full, s, 1);
                s += __shfl_xor_sync(full, s, 2);
                s *= (1.0f / AA);
                f.x -= s; f.y -= s; f.z -= s; f.w -= s;

                // mean-center mb over 16 'af'
                float sm = m0 + m1;
                sm += __shfl_xor_sync(full, sm, 4);
                sm += __shfl_xor_sync(full, sm, 8);
                sm += __shfl_xor_sync(full, sm, 16);
                sm *= (1.0f / AA);
                m0 -= sm; m1 -= sm;

                if (r0 == 0) ((float4*)mfp)[k] = f;
                if (k == 0) { mbp[r0] = m0; mbp[r0 + 8] = m1; }
            }
        }
        __syncthreads();

        // ---- node update + argmax ----
        {
            int n = tid >> 4, a = tid & 15;
            float v = s_nv[tid] * (1.0f / NN);
            int ic = g_in_cnt[n];
            const int* il = g_in_list + n * EE;
            for (int i = 0; i < ic; i++) v += s_mf[(il[i] << 4) + a];
            int oc = g_out_cnt[n];
            const int* ol = g_out_list + n * EE;
            for (int i = 0; i < oc; i++) v += s_mb[(ol[i] << 4) + a];
            __syncthreads();              // mf/mb reads done before q write races? q separate; sync for s_a rewrite safety
            s_q[tid] = v;

            float bv = v; int bi = a;
            #pragma unroll
            for (int m = 1; m < 16; m <<= 1) {
                float ov = __shfl_xor_sync(full, bv, m, 16);
                int   oi = __shfl_xor_sync(full, bi, m, 16);
                if (ov > bv || (ov == bv && oi < bi)) { bv = ov; bi = oi; }
            }
            if (a == 0) s_a[n] = bi;
        }
        __syncthreads();

        // ---- eval current assignment, keep best ----
        do_eval();
    }

    // ---------------- write results ----------------
    if (tid == 0) g_qmax[b] = sh_qmax;
    if (tid < NN) g_amax[b * NN + tid] = s_am[tid];
}

// ---------------- output: concat(q_max[B], a_max[B*N]) as float32 -----------
__global__ void k_out(float* __restrict__ out, int out_size) {
    int i = blockIdx.x * blockDim.x + threadIdx.x;
    if (i >= out_size) return;
    if (out_size >= BB + BB * NN) {
        if (i < BB)                 out[i] = g_qmax[i];
        else if (i < BB + BB * NN)  out[i] = (float)g_amax[i - BB];
    } else if (out_size == BB * NN) {
        out[i] = (float)g_amax[i];
    } else {
        if (i < BB) out[i] = g_qmax[i];
    }
}

// ---------------- launch ----------------------------------------------------
extern "C" void kernel_launch(void* const* d_in, const int* in_sizes, int n_in,
                              void* d_out, int out_size) {
    const float* node_vals = (const float*)d_in[0];
    const float* edge_vals = (const float*)d_in[1];
    const int*   ef        = (const int*)d_in[2];
    const int*   et        = (const int*)d_in[3];
    float* out = (float*)d_out;

    cudaFuncSetAttribute(k_main, cudaFuncAttributeMaxDynamicSharedMemorySize,
                         SMEM_BYTES);

    k_adj<<<1, 128>>>(ef, et);
    k_main<<<BB, 1024, SMEM_BYTES>>>(node_vals, edge_vals, ef, et);

    int tot = BB + BB * NN;
    int span = (out_size > tot) ? out_size : tot;
    k_out<<<(span + 255) / 256, 256>>>(out, out_size);
}

// round 7
// speedup vs baseline: 1.4116x; 1.0402x over previous
#include <cuda_runtime.h>
#include <math.h>

#define BB 512
#define NN 64
#define EE 512
#define AA 16
#define ITERS 8

#define THREADS 512
#define SMEM_BYTES (84 * 1024)

// ---------------- fused persistent kernel: one CTA per batch ----------------
// 512 threads, ~83KB dynamic SMEM -> 2 CTAs/SM so two batches overlap phases.
__global__ void __launch_bounds__(THREADS, 2) k_main(
    const float* __restrict__ node_vals,
    const float* __restrict__ edge_vals,
    const int* __restrict__ ef_g,
    const int* __restrict__ et_g,
    float* __restrict__ out, int out_size)
{
    extern __shared__ float smem[];
    float* s_mf  = smem;                    // 8192 floats (32 KB)
    float* s_mb  = s_mf + EE * AA;          // 8192 floats (32 KB)
    float* s_q   = s_mb + EE * AA;          // 1024 floats (4 KB)
    float* s_nv  = s_q  + NN * AA;          // 1024 floats (4 KB)
    int*   s_ef  = (int*)(s_nv + NN * AA);  // 512
    int*   s_et  = s_ef + EE;               // 512
    int*   s_ino = s_et + EE;               // 65  (in CSR offsets)
    int*   s_out = s_ino + NN + 1;          // 65  (out CSR offsets)
    int*   s_inl = s_out + NN + 1;          // 512 (in edge list, ascending)
    int*   s_onl = s_inl + EE;              // 512 (out edge list, ascending)
    int*   s_a   = s_onl + EE;              // 64  current argmax
    int*   s_am  = s_a  + NN;               // 64  best actions
    float* s_red = (float*)(s_am + NN);     // 16  warp partials

    __shared__ float sh_qmax;
    __shared__ int   sh_flag;

    const int b    = blockIdx.x;
    const int tid  = threadIdx.x;           // 512
    const int lane = tid & 31;
    const int warp = tid >> 5;              // 0..15
    const unsigned full = 0xffffffffu;

    // ---------------- init: load inputs, zero messages ----------------
    {
        const float* nvp = node_vals + (size_t)b * NN * AA;
        float4 z = make_float4(0.f, 0.f, 0.f, 0.f);
        #pragma unroll
        for (int p = 0; p < 2; p++) {
            int i = tid + p * THREADS;      // 0..1023
            float v = nvp[i];
            s_nv[i] = v;
            s_q[i]  = v * (1.0f / NN);
        }
        #pragma unroll
        for (int p = 0; p < 8; p++) {
            ((float4*)s_mf)[tid + p * THREADS] = z;   // wait: 4096 float4 total for mf+mb
        }
        // 8192 floats each = 2048 float4 each; 4096 total -> 8 per thread covers both
        // (first 4 passes hit s_mf, next 4 hit s_mb because they are contiguous)
        s_ef[tid] = ef_g[tid];
        s_et[tid] = et_g[tid];
        if (tid == 0) { sh_qmax = -INFINITY; sh_flag = 0; }
    }
    __syncthreads();

    // ---------------- initial per-node argmax over RAW node_vals -------------
    {
        #pragma unroll
        for (int p = 0; p < 2; p++) {
            int n = (tid >> 4) + p * 32;
            int a = tid & 15;
            float bv = s_nv[n * AA + a]; int bi = a;
            #pragma unroll
            for (int m = 1; m < 16; m <<= 1) {
                float ov = __shfl_xor_sync(full, bv, m, 16);
                int   oi = __shfl_xor_sync(full, bi, m, 16);
                if (ov > bv || (ov == bv && oi < bi)) { bv = ov; bi = oi; }
            }
            if (a == 0) s_a[n] = bi;
        }
    }

    // ---------------- CSR adjacency build (deterministic, ascending e) ------
    {
        if (tid < NN) {                          // in-degree counts
            int c = 0;
            for (int e = 0; e < EE; e++) if (s_et[e] == tid) c++;
            s_ino[tid + 1] = c;
        } else if (tid < 2 * NN) {               // out-degree counts
            int n = tid - NN; int c = 0;
            for (int e = 0; e < EE; e++) if (s_ef[e] == n) c++;
            s_out[n + 1] = c;
        }
        __syncthreads();
        if (tid == 0) {
            s_ino[0] = 0; s_out[0] = 0;
            for (int n = 0; n < NN; n++) {
                s_ino[n + 1] += s_ino[n];
                s_out[n + 1] += s_out[n];
            }
        }
        __syncthreads();
        if (tid < NN) {
            int c = s_ino[tid];
            for (int e = 0; e < EE; e++) if (s_et[e] == tid) s_inl[c++] = e;
        } else if (tid < 2 * NN) {
            int n = tid - NN; int c = s_out[n];
            for (int e = 0; e < EE; e++) if (s_ef[e] == n) s_onl[c++] = e;
        }
    }
    __syncthreads();

    // ---------------- eval helper ----------------
    auto do_eval = [&]() {
        float contrib = 0.f;
        if (tid < NN)
            contrib += s_nv[tid * AA + s_a[tid]] * (1.0f / NN);
        {
            int e  = tid;                        // 512 threads == EE
            int af = s_a[s_ef[e]];
            int at = s_a[s_et[e]];
            contrib += __ldg(&edge_vals[(((size_t)b * EE + e) * AA + af) * AA + at])
                       * (1.0f / EE);
        }
        #pragma unroll
        for (int m = 16; m > 0; m >>= 1)
            contrib += __shfl_xor_sync(full, contrib, m);
        if (lane == 0) s_red[warp] = contrib;
        __syncthreads();
        if (warp == 0) {
            float v = (lane < 16) ? s_red[lane] : 0.f;
            #pragma unroll
            for (int m = 8; m > 0; m >>= 1)
                v += __shfl_xor_sync(full, v, m, 16);
            if (lane == 0) {
                if (v > sh_qmax) { sh_qmax = v; sh_flag = 1; }
                else             { sh_flag = 0; }
            }
        }
        __syncthreads();
        if (sh_flag && tid < NN) s_am[tid] = s_a[tid];
        __syncthreads();
    };

    do_eval();   // iteration-0 eval of raw argmax assignment

    // ---------------- 8 message-passing iterations ----------------
    for (int it = 0; it < ITERS; it++) {
        // ---- message phase: each warp owns 32 edges ----
        {
            int r0 = lane >> 2;            // row 0..7 (also row+8)
            int k  = lane & 3;             // column group (4k..4k+3)
            #pragma unroll 2
            for (int i = 0; i < 32; i++) {
                int e = warp * 32 + i;
                const float4* tile = (const float4*)(edge_vals + (((size_t)b * EE + e) << 8));
                float4 v0 = __ldg(tile + lane);
                float4 v1 = __ldg(tile + 32 + lane);
                const float sc = 1.0f / EE;
                v0.x *= sc; v0.y *= sc; v0.z *= sc; v0.w *= sc;
                v1.x *= sc; v1.y *= sc; v1.z *= sc; v1.w *= sc;

                int nf = s_ef[e], nt = s_et[e];
                const float* qf = s_q + (nf << 4);
                const float* qt = s_q + (nt << 4);
                float* mfp = s_mf + (e << 4);
                float* mbp = s_mb + (e << 4);

                // d[at] = q[to][at] - mf_old[at]  (lane's 4 cols)
                float4 qt4  = ((const float4*)qt)[k];
                float4 mfo4 = ((const float4*)mfp)[k];
                float4 d4 = make_float4(qt4.x - mfo4.x, qt4.y - mfo4.y,
                                        qt4.z - mfo4.z, qt4.w - mfo4.w);
                // c[af] = q[from][af] - mb_old[af] (lane's 2 rows)
                float c0 = qf[r0]     - mbp[r0];
                float c1 = qf[r0 + 8] - mbp[r0 + 8];

                // mb_new[af] = max_at( d[at] + ev[af][at] )
                float m0 = fmaxf(fmaxf(d4.x + v0.x, d4.y + v0.y),
                                 fmaxf(d4.z + v0.z, d4.w + v0.w));
                float m1 = fmaxf(fmaxf(d4.x + v1.x, d4.y + v1.y),
                                 fmaxf(d4.z + v1.z, d4.w + v1.w));
                m0 = fmaxf(m0, __shfl_xor_sync(full, m0, 1));
                m0 = fmaxf(m0, __shfl_xor_sync(full, m0, 2));
                m1 = fmaxf(m1, __shfl_xor_sync(full, m1, 1));
                m1 = fmaxf(m1, __shfl_xor_sync(full, m1, 2));

                // mf_new[at] = max_af( c[af] + ev[af][at] )
                float4 f;
                f.x = fmaxf(c0 + v0.x, c1 + v1.x);
                f.y = fmaxf(c0 + v0.y, c1 + v1.y);
                f.z = fmaxf(c0 + v0.z, c1 + v1.z);
                f.w = fmaxf(c0 + v0.w, c1 + v1.w);
                #pragma unroll
                for (int m = 4; m <= 16; m <<= 1) {
                    f.x = fmaxf(f.x, __shfl_xor_sync(full, f.x, m));
                    f.y = fmaxf(f.y, __shfl_xor_sync(full, f.y, m));
                    f.z = fmaxf(f.z, __shfl_xor_sync(full, f.z, m));
                    f.w = fmaxf(f.w, __shfl_xor_sync(full, f.w, m));
                }

                // mean-center mf over 16 'at'
                float s = f.x + f.y + f.z + f.w;
                s += __shfl_xor_sync(full, s, 1);
                s += __shfl_xor_sync(full, s, 2);
                s *= (1.0f / AA);
                f.x -= s; f.y -= s; f.z -= s; f.w -= s;

                // mean-center mb over 16 'af'
                float sm = m0 + m1;
                sm += __shfl_xor_sync(full, sm, 4);
                sm += __shfl_xor_sync(full, sm, 8);
                sm += __shfl_xor_sync(full, sm, 16);
                sm *= (1.0f / AA);
                m0 -= sm; m1 -= sm;

                if (r0 == 0) ((float4*)mfp)[k] = f;
                if (k == 0) { mbp[r0] = m0; mbp[r0 + 8] = m1; }
            }
        }
        __syncthreads();

        // ---- node update + argmax (two passes of 32 nodes) ----
        {
            #pragma unroll
            for (int p = 0; p < 2; p++) {
                int n = (tid >> 4) + p * 32;
                int a = tid & 15;
                float v = s_nv[n * AA + a] * (1.0f / NN);
                int i0 = s_ino[n], i1 = s_ino[n + 1];
                for (int i = i0; i < i1; i++) v += s_mf[(s_inl[i] << 4) + a];
                int o0 = s_out[n], o1 = s_out[n + 1];
                for (int i = o0; i < o1; i++) v += s_mb[(s_onl[i] << 4) + a];
                s_q[n * AA + a] = v;

                float bv = v; int bi = a;
                #pragma unroll
                for (int m = 1; m < 16; m <<= 1) {
                    float ov = __shfl_xor_sync(full, bv, m, 16);
                    int   oi = __shfl_xor_sync(full, bi, m, 16);
                    if (ov > bv || (ov == bv && oi < bi)) { bv = ov; bi = oi; }
                }
                if (a == 0) s_a[n] = bi;
            }
        }
        __syncthreads();

        // ---- eval current assignment, keep best ----
        do_eval();
    }

    // ---------------- write results directly ----------------
    int tot = BB + BB * NN;
    if (out_size >= tot) {
        if (tid == 0) out[b] = sh_qmax;
        if (tid < NN) out[BB + b * NN + tid] = (float)s_am[tid];
    } else if (out_size == BB * NN) {
        if (tid < NN) out[b * NN + tid] = (float)s_am[tid];
    } else {
        if (tid == 0 && b < out_size) out[b] = sh_qmax;
    }
}

// ---------------- launch ----------------------------------------------------
extern "C" void kernel_launch(void* const* d_in, const int* in_sizes, int n_in,
                              void* d_out, int out_size) {
    const float* node_vals = (const float*)d_in[0];
    const float* edge_vals = (const float*)d_in[1];
    const int*   ef        = (const int*)d_in[2];
    const int*   et        = (const int*)d_in[3];
    float* out = (float*)d_out;

    cudaFuncSetAttribute(k_main, cudaFuncAttributeMaxDynamicSharedMemorySize,
                         SMEM_BYTES);

    k_main<<<BB, THREADS, SMEM_BYTES>>>(node_vals, edge_vals, ef, et,
                                        out, out_size);
}

// round 9
// speedup vs baseline: 1.6000x; 1.1335x over previous
#include <cuda_runtime.h>
#include <math.h>

#define BB 512
#define NN 64
#define EE 512
#define AA 16
#define ITERS 8

#define THREADS 512
#define SMEM_BYTES (84 * 1024)

// ---------------- fused persistent kernel: one CTA per batch ----------------
// 512 threads, ~83KB dynamic SMEM -> 2 CTAs/SM so two batches overlap phases.
__global__ void __launch_bounds__(THREADS, 2) k_main(
    const float* __restrict__ node_vals,
    const float* __restrict__ edge_vals,
    const int* __restrict__ ef_g,
    const int* __restrict__ et_g,
    float* __restrict__ out, int out_size)
{
    extern __shared__ float smem[];
    float* s_mf  = smem;                    // 8192 floats (32 KB)
    float* s_mb  = s_mf + EE * AA;          // 8192 floats (32 KB)
    float* s_q   = s_mb + EE * AA;          // 1024 floats (4 KB)
    float* s_nv  = s_q  + NN * AA;          // 1024 floats (4 KB)
    int*   s_ef  = (int*)(s_nv + NN * AA);  // 512
    int*   s_et  = s_ef + EE;               // 512
    int*   s_ino = s_et + EE;               // 65  (in CSR offsets)
    int*   s_out = s_ino + NN + 1;          // 65  (out CSR offsets)
    int*   s_inl = s_out + NN + 1;          // 512 (in edge list, ascending)
    int*   s_onl = s_inl + EE;              // 512 (out edge list, ascending)
    int*   s_a   = s_onl + EE;              // 64  current argmax
    int*   s_am  = s_a  + NN;               // 64  best actions
    float* s_red = (float*)(s_am + NN);     // 16  warp partials

    __shared__ float sh_qmax;
    __shared__ int   sh_flag;

    const int b    = blockIdx.x;
    const int tid  = threadIdx.x;           // 512
    const int lane = tid & 31;
    const int warp = tid >> 5;              // 0..15
    const unsigned full = 0xffffffffu;

    // ---------------- init: load inputs, zero messages ----------------
    {
        const float* nvp = node_vals + (size_t)b * NN * AA;
        float4 z = make_float4(0.f, 0.f, 0.f, 0.f);
        #pragma unroll
        for (int p = 0; p < 2; p++) {
            int i = tid + p * THREADS;      // 0..1023
            float v = nvp[i];
            s_nv[i] = v;
            s_q[i]  = v * (1.0f / NN);
        }
        #pragma unroll
        for (int p = 0; p < 8; p++)
            ((float4*)s_mf)[tid + p * THREADS] = z;   // covers s_mf then s_mb (contiguous)
        s_ef[tid] = ef_g[tid];
        s_et[tid] = et_g[tid];
        if (tid == 0) { sh_qmax = -INFINITY; sh_flag = 0; }
    }
    __syncthreads();

    // ---------------- initial per-node argmax over RAW node_vals -------------
    {
        #pragma unroll
        for (int p = 0; p < 2; p++) {
            int n = (tid >> 4) + p * 32;
            int a = tid & 15;
            float bv = s_nv[n * AA + a]; int bi = a;
            #pragma unroll
            for (int m = 1; m < 16; m <<= 1) {
                float ov = __shfl_xor_sync(full, bv, m, 16);
                int   oi = __shfl_xor_sync(full, bi, m, 16);
                if (ov > bv || (ov == bv && oi < bi)) { bv = ov; bi = oi; }
            }
            if (a == 0) s_a[n] = bi;
        }
    }

    // ---------------- CSR adjacency build (deterministic, ascending e) ------
    {
        if (tid < NN) {
            int c = 0;
            for (int e = 0; e < EE; e++) if (s_et[e] == tid) c++;
            s_ino[tid + 1] = c;
        } else if (tid < 2 * NN) {
            int n = tid - NN; int c = 0;
            for (int e = 0; e < EE; e++) if (s_ef[e] == n) c++;
            s_out[n + 1] = c;
        }
        __syncthreads();
        if (tid == 0) {
            s_ino[0] = 0; s_out[0] = 0;
            for (int n = 0; n < NN; n++) {
                s_ino[n + 1] += s_ino[n];
                s_out[n + 1] += s_out[n];
            }
        }
        __syncthreads();
        if (tid < NN) {
            int c = s_ino[tid];
            for (int e = 0; e < EE; e++) if (s_et[e] == tid) s_inl[c++] = e;
        } else if (tid < 2 * NN) {
            int n = tid - NN; int c = s_out[n];
            for (int e = 0; e < EE; e++) if (s_ef[e] == n) s_onl[c++] = e;
        }
    }
    __syncthreads();

    // ---------------- eval helper ----------------
    auto do_eval = [&]() {
        float contrib = 0.f;
        if (tid < NN)
            contrib += s_nv[tid * AA + s_a[tid]] * (1.0f / NN);
        {
            int e  = tid;                        // 512 threads == EE
            int af = s_a[s_ef[e]];
            int at = s_a[s_et[e]];
            contrib += __ldg(&edge_vals[(((size_t)b * EE + e) * AA + af) * AA + at])
                       * (1.0f / EE);
        }
        #pragma unroll
        for (int m = 16; m > 0; m >>= 1)
            contrib += __shfl_xor_sync(full, contrib, m);
        if (lane == 0) s_red[warp] = contrib;
        __syncthreads();
        if (warp == 0) {
            float v = (lane < 16) ? s_red[lane] : 0.f;
            #pragma unroll
            for (int m = 8; m > 0; m >>= 1)
                v += __shfl_xor_sync(full, v, m, 16);
            if (lane == 0) {
                if (v > sh_qmax) { sh_qmax = v; sh_flag = 1; }
                else             { sh_flag = 0; }
            }
        }
        __syncthreads();
        if (sh_flag && tid < NN) s_am[tid] = s_a[tid];
        __syncthreads();
    };

    do_eval();   // iteration-0 eval of raw argmax assignment

    const int tsel = lane >> 4;      // which of the warp's 2 concurrent tiles
    const int tl   = lane & 15;      // lane within tile
    const int rg   = tl >> 2;        // row group: rows 4*rg .. 4*rg+3
    const int kg   = tl & 3;         // col group: cols 4*kg .. 4*kg+3

    // ---------------- 8 message-passing iterations ----------------
    for (int it = 0; it < ITERS; it++) {
        // ---- message phase: 16 lanes per tile, 2 tiles per warp, 4x4 blocks ----
        {
            const float sc = 1.0f / EE;
            #pragma unroll 2
            for (int i = 0; i < 16; i++) {
                int e = (warp << 5) + (i << 1) + tsel;
                const float4* tile4 =
                    (const float4*)(edge_vals + (((size_t)b * EE + e) << 8));
                int nf = s_ef[e], nt = s_et[e];
                float* mfp = s_mf + (e << 4);
                float* mbp = s_mb + (e << 4);

                // d[at] = q[to][at] - mf_old[at]   (this lane's 4 cols, group kg)
                float4 qt4  = ((const float4*)(s_q + (nt << 4)))[kg];
                float4 mfo4 = ((const float4*)mfp)[kg];
                float4 d4 = make_float4(qt4.x - mfo4.x, qt4.y - mfo4.y,
                                        qt4.z - mfo4.z, qt4.w - mfo4.w);
                // c[af] = q[from][af] - mb_old[af] (this lane's 4 rows, group rg)
                float4 qf4  = ((const float4*)(s_q + (nf << 4)))[rg];
                float4 mbo4 = ((const float4*)mbp)[rg];
                float4 c4 = make_float4(qf4.x - mbo4.x, qf4.y - mbo4.y,
                                        qf4.z - mbo4.z, qf4.w - mbo4.w);

                float4 f4, m4, v;
                int base = (rg << 4) + kg;      // float4 index of (row 4rg, colgrp kg)

                // j = 0 : row 4rg+0
                v = __ldg(tile4 + base);
                v.x *= sc; v.y *= sc; v.z *= sc; v.w *= sc;
                m4.x = fmaxf(fmaxf(d4.x + v.x, d4.y + v.y),
                             fmaxf(d4.z + v.z, d4.w + v.w));
                f4.x = c4.x + v.x; f4.y = c4.x + v.y;
                f4.z = c4.x + v.z; f4.w = c4.x + v.w;
                // j = 1 : row 4rg+1
                v = __ldg(tile4 + base + 4);
                v.x *= sc; v.y *= sc; v.z *= sc; v.w *= sc;
                m4.y = fmaxf(fmaxf(d4.x + v.x, d4.y + v.y),
                             fmaxf(d4.z + v.z, d4.w + v.w));
                f4.x = fmaxf(f4.x, c4.y + v.x); f4.y = fmaxf(f4.y, c4.y + v.y);
                f4.z = fmaxf(f4.z, c4.y + v.z); f4.w = fmaxf(f4.w, c4.y + v.w);
                // j = 2 : row 4rg+2
                v = __ldg(tile4 + base + 8);
                v.x *= sc; v.y *= sc; v.z *= sc; v.w *= sc;
                m4.z = fmaxf(fmaxf(d4.x + v.x, d4.y + v.y),
                             fmaxf(d4.z + v.z, d4.w + v.w));
                f4.x = fmaxf(f4.x, c4.z + v.x); f4.y = fmaxf(f4.y, c4.z + v.y);
                f4.z = fmaxf(f4.z, c4.z + v.z); f4.w = fmaxf(f4.w, c4.z + v.w);
                // j = 3 : row 4rg+3
                v = __ldg(tile4 + base + 12);
                v.x *= sc; v.y *= sc; v.z *= sc; v.w *= sc;
                m4.w = fmaxf(fmaxf(d4.x + v.x, d4.y + v.y),
                             fmaxf(d4.z + v.z, d4.w + v.w));
                f4.x = fmaxf(f4.x, c4.w + v.x); f4.y = fmaxf(f4.y, c4.w + v.y);
                f4.z = fmaxf(f4.z, c4.w + v.z); f4.w = fmaxf(f4.w, c4.w + v.w);

                // reduce row-maxes (mb) over the 4 col-groups: xor 1, 2 (exact max)
                m4.x = fmaxf(m4.x, __shfl_xor_sync(full, m4.x, 1));
                m4.y = fmaxf(m4.y, __shfl_xor_sync(full, m4.y, 1));
                m4.z = fmaxf(m4.z, __shfl_xor_sync(full, m4.z, 1));
                m4.w = fmaxf(m4.w, __shfl_xor_sync(full, m4.w, 1));
                m4.x = fmaxf(m4.x, __shfl_xor_sync(full, m4.x, 2));
                m4.y = fmaxf(m4.y, __shfl_xor_sync(full, m4.y, 2));
                m4.z = fmaxf(m4.z, __shfl_xor_sync(full, m4.z, 2));
                m4.w = fmaxf(m4.w, __shfl_xor_sync(full, m4.w, 2));

                // reduce col-maxes (mf) over the 4 row-groups: xor 4, 8 (exact max)
                f4.x = fmaxf(f4.x, __shfl_xor_sync(full, f4.x, 4));
                f4.y = fmaxf(f4.y, __shfl_xor_sync(full, f4.y, 4));
                f4.z = fmaxf(f4.z, __shfl_xor_sync(full, f4.z, 4));
                f4.w = fmaxf(f4.w, __shfl_xor_sync(full, f4.w, 4));
                f4.x = fmaxf(f4.x, __shfl_xor_sync(full, f4.x, 8));
                f4.y = fmaxf(f4.y, __shfl_xor_sync(full, f4.y, 8));
                f4.z = fmaxf(f4.z, __shfl_xor_sync(full, f4.z, 8));
                f4.w = fmaxf(f4.w, __shfl_xor_sync(full, f4.w, 8));

                // mean-center mf over 16 'at' (same grouping as R6: serial 4 + xor1 + xor2)
                float s = f4.x + f4.y + f4.z + f4.w;
                s += __shfl_xor_sync(full, s, 1);
                s += __shfl_xor_sync(full, s, 2);
                s *= (1.0f / AA);
                f4.x -= s; f4.y -= s; f4.z -= s; f4.w -= s;

                // mean-center mb over 16 'af' — EXACT R6 sum tree:
                //   a_i = m_i + m_{i+8}   (per-component xor8: rg <-> rg^2)
                //   then ((a_{4g}+a_{4g+1}) + (a_{4g+2}+a_{4g+3}))  (within lane)
                //   then + partner group  (xor4: rg <-> rg^1)
                float4 t4;
                t4.x = m4.x + __shfl_xor_sync(full, m4.x, 8);
                t4.y = m4.y + __shfl_xor_sync(full, m4.y, 8);
                t4.z = m4.z + __shfl_xor_sync(full, m4.z, 8);
                t4.w = m4.w + __shfl_xor_sync(full, m4.w, 8);
                float sm = (t4.x + t4.y) + (t4.z + t4.w);
                sm += __shfl_xor_sync(full, sm, 4);
                sm *= (1.0f / AA);
                m4.x -= sm; m4.y -= sm; m4.z -= sm; m4.w -= sm;

                if (rg == 0) ((float4*)mfp)[kg] = f4;
                if (kg == 0) ((float4*)mbp)[rg] = m4;
            }
        }
        __syncthreads();

        // ---- node update + argmax (two passes of 32 nodes) ----
        {
            #pragma unroll
            for (int p = 0; p < 2; p++) {
                int n = (tid >> 4) + p * 32;
                int a = tid & 15;
                float v = s_nv[n * AA + a] * (1.0f / NN);
                int i0 = s_ino[n], i1 = s_ino[n + 1];
                for (int i = i0; i < i1; i++) v += s_mf[(s_inl[i] << 4) + a];
                int o0 = s_out[n], o1 = s_out[n + 1];
                for (int i = o0; i < o1; i++) v += s_mb[(s_onl[i] << 4) + a];
                s_q[n * AA + a] = v;

                float bv = v; int bi = a;
                #pragma unroll
                for (int m = 1; m < 16; m <<= 1) {
                    float ov = __shfl_xor_sync(full, bv, m, 16);
                    int   oi = __shfl_xor_sync(full, bi, m, 16);
                    if (ov > bv || (ov == bv && oi < bi)) { bv = ov; bi = oi; }
                }
                if (a == 0) s_a[n] = bi;
            }
        }
        __syncthreads();

        // ---- eval current assignment, keep best ----
        do_eval();
    }

    // ---------------- write results directly ----------------
    int tot = BB + BB * NN;
    if (out_size >= tot) {
        if (tid == 0) out[b] = sh_qmax;
        if (tid < NN) out[BB + b * NN + tid] = (float)s_am[tid];
    } else if (out_size == BB * NN) {
        if (tid < NN) out[b * NN + tid] = (float)s_am[tid];
    } else {
        if (tid == 0 && b < out_size) out[b] = sh_qmax;
    }
}

// ---------------- launch ----------------------------------------------------
extern "C" void kernel_launch(void* const* d_in, const int* in_sizes, int n_in,
                              void* d_out, int out_size) {
    const float* node_vals = (const float*)d_in[0];
    const float* edge_vals = (const float*)d_in[1];
    const int*   ef        = (const int*)d_in[2];
    const int*   et        = (const int*)d_in[3];
    float* out = (float*)d_out;

    cudaFuncSetAttribute(k_main, cudaFuncAttributeMaxDynamicSharedMemorySize,
                         SMEM_BYTES);

    k_main<<<BB, THREADS, SMEM_BYTES>>>(node_vals, edge_vals, ef, et,
                                        out, out_size);
}